// round 2
// baseline (speedup 1.0000x reference)
#include <cuda_runtime.h>
#include <math.h>

// ---------------- problem constants ----------------
#define ND   8       // docs
#define FF   64      // frames
#define RR   36      // ROIs
#define DD   1024    // grounding dim
#define MS   16      // max spans
#define WW   10      // span width
#define BH   768     // bert hidden
#define HH   1024    // mlp hidden
#define ED   20      // width embed dim
#define SD   2324    // span dim = 2*768+768+20
#define NSPAN (ND*MS)          // 128
#define NPAIR (NSPAN*NSPAN)    // 16384
#define NEGV (-1e10f)

// ---------------- scratch (device globals; no allocation) ----------------
__device__ __align__(16) float g_hspan[1280*HH];
__device__ __align__(16) float g_scores[1280];
__device__ __align__(16) float g_spans[NSPAN*SD];
__device__ __align__(16) float g_a[NSPAN*HH];
__device__ __align__(16) float g_b[NSPAN*HH];
__device__ __align__(16) float g_h1[NPAIR*HH];
__device__ __align__(16) float g_h2[NPAIR*HH];
__device__ __align__(16) float g_ts[NPAIR];
__device__ __align__(16) float g_att[64*FF*RR];
__device__ float g_Sg[64];
__device__ float g_Sc[64];

// packed f32x2 fma: d = a*b + d (lanewise on 2 floats)
#define FMA2(d,a,b) asm("fma.rn.f32x2 %0, %1, %2, %0;" : "+l"(d) : "l"(a), "l"(b))

// ---------------- tiled fp32 GEMM (f32x2 inner product) ----------------
// MODE 0: C = acc
// MODE 1: C = relu(acc + bias[n])
// MODE 2: A generated on-the-fly as spans[rA,k]*spans[rB,k];
//         C = relu(acc + bias[n] + g_a[rA,n] + g_b[rB,n])
// ASEL: 0=A arg, 1=g_spans, 2=g_h1
// CSEL: 0=g_hspan 1=g_a 2=g_b 3=g_h1 4=g_h2
#define BM 128
#define BN 128
#define BK 16
#define TM 8
#define TN 8

template<int MODE, int ASEL, int CSEL>
__global__ __launch_bounds__(256)
void gemm_kernel(const float* __restrict__ Aarg, const float* __restrict__ B,
                 const float* __restrict__ bias, int M, int N, int K)
{
    const float* A = (ASEL == 0) ? Aarg : (ASEL == 1) ? (const float*)g_spans : (const float*)g_h1;
    float* C = (CSEL == 0) ? g_hspan : (CSEL == 1) ? g_a : (CSEL == 2) ? g_b
             : (CSEL == 3) ? g_h1 : g_h2;

    __shared__ float2 As2[BK][BM];   // duplicated pairs (a,a) -> LDS.64 broadcast
    __shared__ float  Bs[BK][BN];

    int tid = threadIdx.x;
    int m0 = blockIdx.y * BM;
    int n0 = blockIdx.x * BN;

    int ra = tid >> 2;          // 0..63
    int ca = (tid & 3) * 4;     // 0,4,8,12
    int rb = tid >> 5;          // 0..7
    int cb = (tid & 31) * 4;    // 0..124

    unsigned long long acc2[TM][TN/2];
    #pragma unroll
    for (int i = 0; i < TM; i++)
        #pragma unroll
        for (int j = 0; j < TN/2; j++) acc2[i][j] = 0ull;

    int tx = tid & 15, ty = tid >> 4;

    for (int k0 = 0; k0 < K; k0 += BK) {
        #pragma unroll
        for (int e = 0; e < 2; e++) {
            int row = m0 + ra + e*64;
            int k = k0 + ca;
            float4 v = make_float4(0.f,0.f,0.f,0.f);
            if (k < K) {
                if (MODE == 2) {
                    int ii = (row >> 4) & 15, jj = row & 15, sv = row >> 8;
                    int rA = (sv >> 3)*MS + ii;
                    int rB = (sv & 7)*MS + jj;
                    float4 x = *(const float4*)(A + (long)rA*K + k);
                    float4 y = *(const float4*)(A + (long)rB*K + k);
                    v = make_float4(x.x*y.x, x.y*y.y, x.z*y.z, x.w*y.w);
                } else {
                    v = *(const float4*)(A + (long)row*K + k);
                }
            }
            As2[ca+0][ra + e*64] = make_float2(v.x, v.x);
            As2[ca+1][ra + e*64] = make_float2(v.y, v.y);
            As2[ca+2][ra + e*64] = make_float2(v.z, v.z);
            As2[ca+3][ra + e*64] = make_float2(v.w, v.w);
        }
        #pragma unroll
        for (int e = 0; e < 2; e++) {
            int k = k0 + rb + e*8;
            float4 v = make_float4(0.f,0.f,0.f,0.f);
            if (k < K) v = *(const float4*)(B + (long)k*N + n0 + cb);
            *(float4*)&Bs[rb+e*8][cb] = v;
        }
        __syncthreads();
        #pragma unroll
        for (int kk = 0; kk < BK; kk++) {
            unsigned long long rm2[TM], rb2[TN/2];
            #pragma unroll
            for (int i = 0; i < TM; i++)
                rm2[i] = *(const unsigned long long*)&As2[kk][ty*TM + i];
            #pragma unroll
            for (int j = 0; j < TN/2; j++)
                rb2[j] = *(const unsigned long long*)&Bs[kk][tx*TN + 2*j];
            #pragma unroll
            for (int i = 0; i < TM; i++)
                #pragma unroll
                for (int j = 0; j < TN/2; j++)
                    FMA2(acc2[i][j], rm2[i], rb2[j]);
        }
        __syncthreads();
    }

    #pragma unroll
    for (int i = 0; i < TM; i++) {
        int row = m0 + ty*TM + i;
        int rA = 0, rB = 0;
        if (MODE == 2) {
            int ii = (row >> 4) & 15, jj = row & 15, sv = row >> 8;
            rA = (sv >> 3)*MS + ii;
            rB = (sv & 7)*MS + jj;
        }
        #pragma unroll
        for (int j = 0; j < TN/2; j++) {
            int col = n0 + tx*TN + 2*j;
            float v0 = __uint_as_float((unsigned)(acc2[i][j] & 0xffffffffull));
            float v1 = __uint_as_float((unsigned)(acc2[i][j] >> 32));
            if (MODE >= 1) { v0 += bias[col]; v1 += bias[col+1]; }
            if (MODE == 2) {
                v0 += g_a[rA*HH + col]   + g_b[rB*HH + col];
                v1 += g_a[rA*HH + col+1] + g_b[rB*HH + col+1];
            }
            if (MODE >= 1) { v0 = fmaxf(v0, 0.f); v1 = fmaxf(v1, 0.f); }
            *(float2*)(C + (long)row*N + col) = make_float2(v0, v1);
        }
    }
}

// ---------------- matvec: out[r] = dot(A[r,0:1024], w) + bias[0] ----------------
// ASEL: 0=g_hspan -> g_scores, 1=g_h2 -> g_ts
template<int ASEL>
__global__ void matvec1024(const float* __restrict__ w,
                           const float* __restrict__ bias, int M)
{
    const float* A = (ASEL == 0) ? g_hspan : g_h2;
    float* out = (ASEL == 0) ? g_scores : g_ts;
    int warp = (blockIdx.x*blockDim.x + threadIdx.x) >> 5;
    int lane = threadIdx.x & 31;
    if (warp >= M) return;
    const float4* a4 = (const float4*)(A + (long)warp*1024);
    const float4* w4 = (const float4*)w;
    float s = 0.f;
    #pragma unroll 4
    for (int c = lane; c < 256; c += 32) {
        float4 x = a4[c], y = w4[c];
        s += x.x*y.x + x.y*y.y + x.z*y.z + x.w*y.w;
    }
    #pragma unroll
    for (int o = 16; o > 0; o >>= 1) s += __shfl_xor_sync(0xffffffffu, s, o);
    if (lane == 0) out[warp] = s + bias[0];
}

// ---------------- span softmax + assemble spans ----------------
__global__ void assemble_kernel(const float* __restrict__ se, const float* __restrict__ cont,
                                const int* __restrict__ width, const float* __restrict__ wemb)
{
    int b = blockIdx.x;        // span index 0..127
    int tid = threadIdx.x;     // 256
    __shared__ float attn[WW];
    int w = width[b];
    if (tid == 0) {
        float sc[WW]; float mx = -INFINITY;
        for (int t = 0; t < WW; t++) {
            sc[t] = (t < w) ? g_scores[b*WW + t] : NEGV;
            mx = fmaxf(mx, sc[t]);
        }
        float sum = 0.f;
        for (int t = 0; t < WW; t++) { sc[t] = expf(sc[t] - mx); sum += sc[t]; }
        for (int t = 0; t < WW; t++) attn[t] = sc[t]/sum;
    }
    __syncthreads();
    float* row = g_spans + (long)b*SD;
    for (int k = tid; k < 2*BH; k += 256) row[k] = se[(long)b*2*BH + k];
    for (int d = tid; d < BH; d += 256) {
        float acc = 0.f;
        #pragma unroll
        for (int t = 0; t < WW; t++) acc += attn[t]*cont[((long)b*WW + t)*BH + d];
        row[2*BH + d] = acc;
    }
    if (tid < ED) row[2*BH + BH + tid] = wemb[min(w,4)*ED + tid];
}

// ---------------- grounding: att[s,v,i,j] = doc[s,i,:]·img[v,j,:] ----------------
__global__ void att_kernel(const float* __restrict__ doc, const float* __restrict__ img)
{
    int b = blockIdx.x, s = b >> 3, v = b & 7;
    for (int idx = threadIdx.x; idx < FF*RR; idx += blockDim.x) {
        int i = idx / RR, j = idx % RR;
        const float4* dr = (const float4*)(doc + (long)(s*FF + i)*DD);
        const float4* ir = (const float4*)(img + (long)(v*RR + j)*DD);
        float acc = 0.f;
        #pragma unroll 8
        for (int c = 0; c < DD/4; c++) {
            float4 x = dr[c], y = ir[c];
            acc += x.x*y.x + x.y*y.y + x.z*y.z + x.w*y.w;
        }
        g_att[((long)b*FF + i)*RR + j] = acc;
    }
}

// ---------------- grounding reduce -> S_g ----------------
__global__ void ground_reduce(const float* __restrict__ tm, const float* __restrict__ im)
{
    __shared__ float sh[FF][RR+1];
    __shared__ float stm[FF], sim[RR];
    __shared__ float red[FF];
    int b = blockIdx.x, s = b >> 3, v = b & 7;
    int tid = threadIdx.x; // 64
    if (tid < FF) stm[tid] = tm[s*FF + tid];
    if (tid < RR) sim[tid] = im[v*RR + tid];
    __syncthreads();
    for (int idx = tid; idx < FF*RR; idx += 64) {
        int i = idx / RR, j = idx % RR;
        float a = g_att[((long)b*FF + i)*RR + j];
        float m = stm[i]*sim[j];
        a *= m;
        if (a == 0.f) a = NEGV;
        sh[i][j] = a;
    }
    __syncthreads();
    float part = 0.f;
    {   // softmax over j of (att * im[j]); weights = mask; dot with att
        int i = tid;
        float mx = -INFINITY;
        for (int j = 0; j < RR; j++) mx = fmaxf(mx, sh[i][j]*sim[j]);
        float ssum = 0.f;
        for (int j = 0; j < RR; j++) ssum += expf(sh[i][j]*sim[j] - mx);
        for (int j = 0; j < RR; j++) {
            float aw = expf(sh[i][j]*sim[j] - mx)/ssum * stm[i]*sim[j];
            part += aw * sh[i][j];
        }
    }
    if (tid < RR) { // softmax over frame axis i
        int j = tid;
        float mx = -INFINITY;
        for (int i = 0; i < FF; i++) mx = fmaxf(mx, sh[i][j]);
        float ssum = 0.f;
        for (int i = 0; i < FF; i++) ssum += expf(sh[i][j] - mx);
        for (int i = 0; i < FF; i++) {
            float aw = expf(sh[i][j] - mx)/ssum * stm[i]*sim[j];
            part += aw * sh[i][j];
        }
    }
    red[tid] = part;
    __syncthreads();
    for (int o = 32; o > 0; o >>= 1) {
        if (tid < o) red[tid] += red[tid+o];
        __syncthreads();
    }
    if (tid == 0) g_Sg[b] = red[0];
}

// ---------------- adaptive S_c ----------------
__global__ void sc_kernel(const float* __restrict__ m1)
{
    int b = blockIdx.x, s = b >> 3, v = b & 7;
    const float* T = g_ts + (long)b*MS*MS;
    int lane = threadIdx.x;
    float cs = 0.f, cv = 0.f;
    for (int k = 0; k < MS; k++) { cs += m1[s*MS+k]; cv += m1[v*MS+k]; }
    float max1 = -INFINITY, max2 = -INFINITY;
    if (lane < MS) {
        float rm = 0.f;
        for (int j = 0; j < MS; j++) rm += T[lane*MS+j]*m1[v*MS+j];
        rm /= cv;
        if (m1[s*MS+lane] > 0.f) max1 = rm;
        float cm = 0.f;
        for (int i = 0; i < MS; i++) cm += T[i*MS+lane]*m1[s*MS+i];
        cm /= cs;
        if (m1[v*MS+lane] > 0.f) max2 = cm;
    }
    for (int o = 16; o > 0; o >>= 1) {
        max1 = fmaxf(max1, __shfl_xor_sync(0xffffffffu, max1, o));
        max2 = fmaxf(max2, __shfl_xor_sync(0xffffffffu, max2, o));
    }
    if (lane == 0) g_Sc[b] = 0.5f*(max1 + max2);
}

// ---------------- final loss ----------------
__global__ void loss_kernel(float* __restrict__ out)
{
    if (threadIdx.x != 0) return;
    float mg[8][8], mgT[8][8], mc[8][8];
    for (int s = 0; s < 8; s++) {
        float mx = -INFINITY;
        for (int v = 0; v < 8; v++) mx = fmaxf(mx, g_Sg[s*8+v]);
        float sum = 0.f;
        for (int v = 0; v < 8; v++) { mg[s][v] = expf(g_Sg[s*8+v]-mx); sum += mg[s][v]; }
        for (int v = 0; v < 8; v++) mg[s][v] /= sum;
    }
    for (int v = 0; v < 8; v++) {
        float mx = -INFINITY;
        for (int s = 0; s < 8; s++) mx = fmaxf(mx, g_Sg[s*8+v]);
        float sum = 0.f;
        for (int s = 0; s < 8; s++) { mgT[v][s] = expf(g_Sg[s*8+v]-mx); sum += mgT[v][s]; }
        for (int s = 0; s < 8; s++) mgT[v][s] /= sum;
    }
    for (int s = 0; s < 8; s++) {
        float mx = -INFINITY;
        for (int v = 0; v < 8; v++) mx = fmaxf(mx, g_Sc[s*8+v]);
        float sum = 0.f;
        for (int v = 0; v < 8; v++) { mc[s][v] = expf(g_Sc[s*8+v]-mx); sum += mc[s][v]; }
        for (int v = 0; v < 8; v++) mc[s][v] /= sum;
    }
    float loss = 0.f;
    for (int s = 0; s < 8; s++) {
        float t = 0.f;
        for (int v = 0; v < 8; v++) t += mg[s][v]*mc[s][v];
        loss += logf(t);
    }
    for (int v = 0; v < 8; v++) {
        float t = 0.f;
        for (int s = 0; s < 8; s++) t += mgT[v][s]*mc[v][s];
        loss += logf(t);
    }
    out[0] = -loss/(float)ND;
}

// ---------------- host ----------------
extern "C" void kernel_launch(void* const* d_in, const int* in_sizes, int n_in,
                              void* d_out, int out_size)
{
    const float* doc  = (const float*)d_in[0];
    const float* img  = (const float*)d_in[1];
    const float* tm   = (const float*)d_in[2];
    const float* im   = (const float*)d_in[3];
    const float* se   = (const float*)d_in[4];
    const float* cont = (const float*)d_in[5];
    const int*   width= (const int*)  d_in[6];
    const float* m1   = (const float*)d_in[7];
    const float* aw1  = (const float*)d_in[8];
    const float* ab1  = (const float*)d_in[9];
    const float* aw2  = (const float*)d_in[10];
    const float* ab2  = (const float*)d_in[11];
    const float* wemb = (const float*)d_in[12];
    const float* pw1  = (const float*)d_in[13];
    const float* pb1  = (const float*)d_in[14];
    const float* pw2  = (const float*)d_in[15];
    const float* pb2  = (const float*)d_in[16];
    const float* pw3  = (const float*)d_in[17];
    const float* pb3  = (const float*)d_in[18];

    // span attention: h = relu(cont @ aw1 + ab1); scores = h @ aw2 + ab2
    gemm_kernel<1,0,0><<<dim3(HH/BN, 1280/BM), 256>>>(cont, aw1, ab1, 1280, HH, BH);
    matvec1024<0><<<(1280*32+255)/256, 256>>>(aw2, ab2, 1280);
    assemble_kernel<<<NSPAN, 256>>>(se, cont, width, wemb);

    // a = spans@w1[:SD], b = spans@w1[SD:2SD]
    gemm_kernel<0,1,1><<<dim3(HH/BN, NSPAN/BM), 256>>>(nullptr, pw1,                 nullptr, NSPAN, HH, SD);
    gemm_kernel<0,1,2><<<dim3(HH/BN, NSPAN/BM), 256>>>(nullptr, pw1 + (long)SD*HH,   nullptr, NSPAN, HH, SD);
    // h1 = relu(prod @ w1[2SD:] + a + b + b1)
    gemm_kernel<2,1,3><<<dim3(HH/BN, NPAIR/BM), 256>>>(nullptr, pw1 + (long)2*SD*HH, pb1, NPAIR, HH, SD);
    // h2 = relu(h1 @ w2 + b2)
    gemm_kernel<1,2,4><<<dim3(HH/BN, NPAIR/BM), 256>>>(nullptr, pw2, pb2, NPAIR, HH, HH);
    // ts = h2 @ w3 + b3
    matvec1024<1><<<(NPAIR*32+255)/256, 256>>>(pw3, pb3, NPAIR);

    // grounding
    att_kernel<<<64, 256>>>(doc, img);
    ground_reduce<<<64, 64>>>(tm, im);

    // adaptive S_c + final loss
    sc_kernel<<<64, 32>>>(m1);
    loss_kernel<<<1, 32>>>((float*)d_out);
}

// round 5
// speedup vs baseline: 1.1560x; 1.1560x over previous
#include <cuda_runtime.h>
#include <math.h>

// ---------------- problem constants ----------------
#define ND   8
#define FF   64
#define RR   36
#define DD   1024
#define MS   16
#define WW   10
#define BH   768
#define HH   1024
#define ED   20
#define SD   2324
#define NSPAN (ND*MS)          // 128
#define NPAIR (NSPAN*NSPAN)    // 16384
#define NEGV (-1e10f)

// ---------------- scratch ----------------
__device__ __align__(16) float g_hspan[1280*HH];
__device__ __align__(16) float g_scores[1280];
__device__ __align__(16) float g_spans[NSPAN*SD];
__device__ __align__(16) float g_a[NSPAN*HH];
__device__ __align__(16) float g_b[NSPAN*HH];
__device__ __align__(16) float g_h1[NPAIR*HH];
__device__ __align__(16) float g_h2[NPAIR*HH];
__device__ __align__(16) float g_ts[NPAIR];
__device__ __align__(16) float g_att[64*FF*RR];
__device__ float g_Sg[64];
__device__ float g_Sc[64];

#define FMA2(d,a,b) asm("fma.rn.f32x2 %0, %1, %2, %0;" : "+l"(d) : "l"(a), "l"(b))

// ---------------- double-buffered fp32 GEMM (FFMA2 core) ----------------
// MODE 0: C = acc
// MODE 1: C = relu(acc + bias[n])
// MODE 2: A on-the-fly = spans[rA,k]*spans[rB,k]; C = relu(acc+bias+g_a[rA]+g_b[rB])
// ASEL: 0=Aarg 1=g_spans 2=g_h1 ; CSEL: 0=g_hspan 3=g_h1 4=g_h2
#define BM 128
#define BN 128
#define BK 8
#define TM 8
#define TN 8

template<int MODE, int ASEL, int CSEL>
__global__ __launch_bounds__(256, 2)
void gemm_kernel(const float* __restrict__ Aarg, const float* __restrict__ B,
                 const float* __restrict__ bias, int M, int N, int K)
{
    const float* A = (ASEL == 0) ? Aarg : (ASEL == 1) ? (const float*)g_spans : (const float*)g_h1;
    float* C = (CSEL == 0) ? g_hspan : (CSEL == 3) ? g_h1 : g_h2;

    __shared__ float2 As2[2][BK][BM];   // duplicated (a,a) pairs
    __shared__ float  Bs[2][BK][BN];

    int tid = threadIdx.x;
    int m0 = blockIdx.y * BM;
    int n0 = blockIdx.x * BN;

    // A tile loader: 128 rows x 8 cols -> 4 floats/thread
    int la_row = tid >> 1;
    int la_col = (tid & 1) * 4;
    // B tile loader: 8 rows x 128 cols -> 4 floats/thread
    int lb_row = tid >> 5;
    int lb_col = (tid & 31) * 4;

    // precompute MODE2 source rows for the A loader
    int ld_rA = 0, ld_rB = 0;
    {
        int row = m0 + la_row;
        int ii = (row >> 4) & 15, jj = row & 15, sv = row >> 8;
        ld_rA = (sv >> 3)*MS + ii;
        ld_rB = (sv & 7)*MS + jj;
    }

    unsigned long long acc2[TM][TN/2];
    #pragma unroll
    for (int i = 0; i < TM; i++)
        #pragma unroll
        for (int j = 0; j < TN/2; j++) acc2[i][j] = 0ull;

    int tx = tid & 15, ty = tid >> 4;
    int ntiles = (K + BK - 1) / BK;

    float4 aReg, bReg;
    // --- load tile 0 ---
    {
        int k = la_col;
        aReg = make_float4(0.f,0.f,0.f,0.f);
        if (k < K) {
            if (MODE == 2) {
                float4 x = *(const float4*)(A + (long)ld_rA*K + k);
                float4 y = *(const float4*)(A + (long)ld_rB*K + k);
                aReg = make_float4(x.x*y.x, x.y*y.y, x.z*y.z, x.w*y.w);
            } else {
                aReg = *(const float4*)(A + (long)(m0+la_row)*K + k);
            }
        }
        bReg = make_float4(0.f,0.f,0.f,0.f);
        if (lb_row < K) bReg = *(const float4*)(B + (long)lb_row*N + n0 + lb_col);
    }
    As2[0][la_col+0][la_row] = make_float2(aReg.x, aReg.x);
    As2[0][la_col+1][la_row] = make_float2(aReg.y, aReg.y);
    As2[0][la_col+2][la_row] = make_float2(aReg.z, aReg.z);
    As2[0][la_col+3][la_row] = make_float2(aReg.w, aReg.w);
    *(float4*)&Bs[0][lb_row][lb_col] = bReg;
    __syncthreads();

    for (int t = 0; t < ntiles; t++) {
        int cur = t & 1, nxt = cur ^ 1;
        bool more = (t + 1 < ntiles);
        if (more) {
            int k0 = (t + 1) * BK;
            int k = k0 + la_col;
            aReg = make_float4(0.f,0.f,0.f,0.f);
            if (k < K) {
                if (MODE == 2) {
                    float4 x = *(const float4*)(A + (long)ld_rA*K + k);
                    float4 y = *(const float4*)(A + (long)ld_rB*K + k);
                    aReg = make_float4(x.x*y.x, x.y*y.y, x.z*y.z, x.w*y.w);
                } else {
                    aReg = *(const float4*)(A + (long)(m0+la_row)*K + k);
                }
            }
            int kb = k0 + lb_row;
            bReg = make_float4(0.f,0.f,0.f,0.f);
            if (kb < K) bReg = *(const float4*)(B + (long)kb*N + n0 + lb_col);
        }
        #pragma unroll
        for (int kk = 0; kk < BK; kk++) {
            unsigned long long rm2[TM], rb2[TN/2];
            #pragma unroll
            for (int i = 0; i < TM; i++)
                rm2[i] = *(const unsigned long long*)&As2[cur][kk][ty*TM + i];
            #pragma unroll
            for (int j = 0; j < TN/2; j++)
                rb2[j] = *(const unsigned long long*)&Bs[cur][kk][tx*TN + 2*j];
            #pragma unroll
            for (int i = 0; i < TM; i++)
                #pragma unroll
                for (int j = 0; j < TN/2; j++)
                    FMA2(acc2[i][j], rm2[i], rb2[j]);
        }
        if (more) {
            As2[nxt][la_col+0][la_row] = make_float2(aReg.x, aReg.x);
            As2[nxt][la_col+1][la_row] = make_float2(aReg.y, aReg.y);
            As2[nxt][la_col+2][la_row] = make_float2(aReg.z, aReg.z);
            As2[nxt][la_col+3][la_row] = make_float2(aReg.w, aReg.w);
            *(float4*)&Bs[nxt][lb_row][lb_col] = bReg;
        }
        __syncthreads();
    }

    #pragma unroll
    for (int i = 0; i < TM; i++) {
        int row = m0 + ty*TM + i;
        int rA = 0, rB = 0;
        if (MODE == 2) {
            int ii = (row >> 4) & 15, jj = row & 15, sv = row >> 8;
            rA = (sv >> 3)*MS + ii;
            rB = (sv & 7)*MS + jj;
        }
        #pragma unroll
        for (int j = 0; j < TN/2; j++) {
            int col = n0 + tx*TN + 2*j;
            float v0 = __uint_as_float((unsigned)(acc2[i][j] & 0xffffffffull));
            float v1 = __uint_as_float((unsigned)(acc2[i][j] >> 32));
            if (MODE >= 1) { v0 += bias[col]; v1 += bias[col+1]; }
            if (MODE == 2) {
                v0 += g_a[rA*HH + col]   + g_b[rB*HH + col];
                v1 += g_a[rA*HH + col+1] + g_b[rB*HH + col+1];
            }
            if (MODE >= 1) { v0 = fmaxf(v0, 0.f); v1 = fmaxf(v1, 0.f); }
            *(float2*)(C + (long)row*N + col) = make_float2(v0, v1);
        }
    }
}

// ---------------- zero g_a / g_b ----------------
__global__ void zero_ab_kernel()
{
    int i = blockIdx.x*blockDim.x + threadIdx.x;   // 32768 float4 per array
    float4 z = make_float4(0.f,0.f,0.f,0.f);
    ((float4*)g_a)[i] = z;
    ((float4*)g_b)[i] = z;
}

// ---------------- split-K GEMM computing g_a and g_b together ----------------
// out cols 0..1023 -> g_a, 1024..2047 -> g_b ; split over blockIdx.y K-slices
// KSLC MUST be a multiple of 4 so float4 A loads stay 16B-aligned.
#define KS 8
#define KSLC 292   // 8*292 = 2336 >= 2324; multiple of 4 (alignment!)

__global__ __launch_bounds__(256, 2)
void gemm_ab_kernel(const float* __restrict__ pw1)
{
    __shared__ float2 As2[BK][BM];
    __shared__ float  Bs[BK][BN];

    int tid = threadIdx.x;
    int n0 = blockIdx.x * BN;          // 0..1920 over 2048
    int kstart = blockIdx.y * KSLC;
    int kend = min(kstart + KSLC, SD);

    const float* Bsel = (n0 < HH) ? pw1 + n0 : pw1 + (long)SD*HH + (n0 - HH);
    float* Cout = (n0 < HH) ? g_a + n0 : g_b + (n0 - HH);

    int la_row = tid >> 1;
    int la_col = (tid & 1) * 4;
    int lb_row = tid >> 5;
    int lb_col = (tid & 31) * 4;

    unsigned long long acc2[TM][TN/2];
    #pragma unroll
    for (int i = 0; i < TM; i++)
        #pragma unroll
        for (int j = 0; j < TN/2; j++) acc2[i][j] = 0ull;

    int tx = tid & 15, ty = tid >> 4;

    for (int k0 = kstart; k0 < kend; k0 += BK) {
        {
            int k = k0 + la_col;
            float4 v = make_float4(0.f,0.f,0.f,0.f);
            if (k < kend) v = *(const float4*)(g_spans + (long)la_row*SD + k);
            As2[la_col+0][la_row] = make_float2(v.x, v.x);
            As2[la_col+1][la_row] = make_float2(v.y, v.y);
            As2[la_col+2][la_row] = make_float2(v.z, v.z);
            As2[la_col+3][la_row] = make_float2(v.w, v.w);
        }
        {
            int k = k0 + lb_row;
            float4 v = make_float4(0.f,0.f,0.f,0.f);
            if (k < kend) v = *(const float4*)(Bsel + (long)k*HH + lb_col);
            *(float4*)&Bs[lb_row][lb_col] = v;
        }
        __syncthreads();
        #pragma unroll
        for (int kk = 0; kk < BK; kk++) {
            unsigned long long rm2[TM], rb2[TN/2];
            #pragma unroll
            for (int i = 0; i < TM; i++)
                rm2[i] = *(const unsigned long long*)&As2[kk][ty*TM + i];
            #pragma unroll
            for (int j = 0; j < TN/2; j++)
                rb2[j] = *(const unsigned long long*)&Bs[kk][tx*TN + 2*j];
            #pragma unroll
            for (int i = 0; i < TM; i++)
                #pragma unroll
                for (int j = 0; j < TN/2; j++)
                    FMA2(acc2[i][j], rm2[i], rb2[j]);
        }
        __syncthreads();
    }

    #pragma unroll
    for (int i = 0; i < TM; i++) {
        int row = ty*TM + i;
        #pragma unroll
        for (int j = 0; j < TN/2; j++) {
            int col = tx*TN + 2*j;
            float v0 = __uint_as_float((unsigned)(acc2[i][j] & 0xffffffffull));
            float v1 = __uint_as_float((unsigned)(acc2[i][j] >> 32));
            atomicAdd(Cout + (long)row*HH + col,     v0);
            atomicAdd(Cout + (long)row*HH + col + 1, v1);
        }
    }
}

// ---------------- matvec: out[r] = dot(A[r,0:1024], w) + bias[0] ----------------
template<int ASEL>
__global__ void matvec1024(const float* __restrict__ w,
                           const float* __restrict__ bias, int M)
{
    const float* A = (ASEL == 0) ? g_hspan : g_h2;
    float* out = (ASEL == 0) ? g_scores : g_ts;
    int warp = (blockIdx.x*blockDim.x + threadIdx.x) >> 5;
    int lane = threadIdx.x & 31;
    if (warp >= M) return;
    const float4* a4 = (const float4*)(A + (long)warp*1024);
    const float4* w4 = (const float4*)w;
    float s = 0.f;
    #pragma unroll 4
    for (int c = lane; c < 256; c += 32) {
        float4 x = a4[c], y = w4[c];
        s += x.x*y.x + x.y*y.y + x.z*y.z + x.w*y.w;
    }
    #pragma unroll
    for (int o = 16; o > 0; o >>= 1) s += __shfl_xor_sync(0xffffffffu, s, o);
    if (lane == 0) out[warp] = s + bias[0];
}

// ---------------- span softmax + assemble spans ----------------
__global__ void assemble_kernel(const float* __restrict__ se, const float* __restrict__ cont,
                                const int* __restrict__ width, const float* __restrict__ wemb)
{
    int b = blockIdx.x;
    int tid = threadIdx.x;
    __shared__ float attn[WW];
    int w = width[b];
    if (tid == 0) {
        float sc[WW]; float mx = -INFINITY;
        for (int t = 0; t < WW; t++) {
            sc[t] = (t < w) ? g_scores[b*WW + t] : NEGV;
            mx = fmaxf(mx, sc[t]);
        }
        float sum = 0.f;
        for (int t = 0; t < WW; t++) { sc[t] = expf(sc[t] - mx); sum += sc[t]; }
        for (int t = 0; t < WW; t++) attn[t] = sc[t]/sum;
    }
    __syncthreads();
    float* row = g_spans + (long)b*SD;
    for (int k = tid; k < 2*BH; k += 256) row[k] = se[(long)b*2*BH + k];
    for (int d = tid; d < BH; d += 256) {
        float acc = 0.f;
        #pragma unroll
        for (int t = 0; t < WW; t++) acc += attn[t]*cont[((long)b*WW + t)*BH + d];
        row[2*BH + d] = acc;
    }
    if (tid < ED) row[2*BH + BH + tid] = wemb[min(w,4)*ED + tid];
}

// ---------------- grounding: att[s,v,i,j] = doc[s,i,:]·img[v,j,:] ----------------
__global__ void att_kernel(const float* __restrict__ doc, const float* __restrict__ img)
{
    int b = blockIdx.x, s = b >> 3, v = b & 7;
    for (int idx = threadIdx.x; idx < FF*RR; idx += blockDim.x) {
        int i = idx / RR, j = idx % RR;
        const float4* dr = (const float4*)(doc + (long)(s*FF + i)*DD);
        const float4* ir = (const float4*)(img + (long)(v*RR + j)*DD);
        float acc = 0.f;
        #pragma unroll 8
        for (int c = 0; c < DD/4; c++) {
            float4 x = dr[c], y = ir[c];
            acc += x.x*y.x + x.y*y.y + x.z*y.z + x.w*y.w;
        }
        g_att[((long)b*FF + i)*RR + j] = acc;
    }
}

// ---------------- grounding reduce -> S_g ----------------
__global__ void ground_reduce(const float* __restrict__ tm, const float* __restrict__ im)
{
    __shared__ float sh[FF][RR+1];
    __shared__ float stm[FF], sim[RR];
    __shared__ float red[FF];
    int b = blockIdx.x, s = b >> 3, v = b & 7;
    int tid = threadIdx.x; // 64
    if (tid < FF) stm[tid] = tm[s*FF + tid];
    if (tid < RR) sim[tid] = im[v*RR + tid];
    __syncthreads();
    for (int idx = tid; idx < FF*RR; idx += 64) {
        int i = idx / RR, j = idx % RR;
        float a = g_att[((long)b*FF + i)*RR + j];
        float m = stm[i]*sim[j];
        a *= m;
        if (a == 0.f) a = NEGV;
        sh[i][j] = a;
    }
    __syncthreads();
    float part = 0.f;
    {
        int i = tid;
        float mx = -INFINITY;
        for (int j = 0; j < RR; j++) mx = fmaxf(mx, sh[i][j]*sim[j]);
        float ssum = 0.f;
        for (int j = 0; j < RR; j++) ssum += expf(sh[i][j]*sim[j] - mx);
        for (int j = 0; j < RR; j++) {
            float aw = expf(sh[i][j]*sim[j] - mx)/ssum * stm[i]*sim[j];
            part += aw * sh[i][j];
        }
    }
    if (tid < RR) {
        int j = tid;
        float mx = -INFINITY;
        for (int i = 0; i < FF; i++) mx = fmaxf(mx, sh[i][j]);
        float ssum = 0.f;
        for (int i = 0; i < FF; i++) ssum += expf(sh[i][j] - mx);
        for (int i = 0; i < FF; i++) {
            float aw = expf(sh[i][j] - mx)/ssum * stm[i]*sim[j];
            part += aw * sh[i][j];
        }
    }
    red[tid] = part;
    __syncthreads();
    for (int o = 32; o > 0; o >>= 1) {
        if (tid < o) red[tid] += red[tid+o];
        __syncthreads();
    }
    if (tid == 0) g_Sg[b] = red[0];
}

// ---------------- adaptive S_c ----------------
__global__ void sc_kernel(const float* __restrict__ m1)
{
    int b = blockIdx.x, s = b >> 3, v = b & 7;
    const float* T = g_ts + (long)b*MS*MS;
    int lane = threadIdx.x;
    float cs = 0.f, cv = 0.f;
    for (int k = 0; k < MS; k++) { cs += m1[s*MS+k]; cv += m1[v*MS+k]; }
    float max1 = -INFINITY, max2 = -INFINITY;
    if (lane < MS) {
        float rm = 0.f;
        for (int j = 0; j < MS; j++) rm += T[lane*MS+j]*m1[v*MS+j];
        rm /= cv;
        if (m1[s*MS+lane] > 0.f) max1 = rm;
        float cm = 0.f;
        for (int i = 0; i < MS; i++) cm += T[i*MS+lane]*m1[s*MS+i];
        cm /= cs;
        if (m1[v*MS+lane] > 0.f) max2 = cm;
    }
    for (int o = 16; o > 0; o >>= 1) {
        max1 = fmaxf(max1, __shfl_xor_sync(0xffffffffu, max1, o));
        max2 = fmaxf(max2, __shfl_xor_sync(0xffffffffu, max2, o));
    }
    if (lane == 0) g_Sc[b] = 0.5f*(max1 + max2);
}

// ---------------- final loss ----------------
__global__ void loss_kernel(float* __restrict__ out)
{
    if (threadIdx.x != 0) return;
    float mg[8][8], mgT[8][8], mc[8][8];
    for (int s = 0; s < 8; s++) {
        float mx = -INFINITY;
        for (int v = 0; v < 8; v++) mx = fmaxf(mx, g_Sg[s*8+v]);
        float sum = 0.f;
        for (int v = 0; v < 8; v++) { mg[s][v] = expf(g_Sg[s*8+v]-mx); sum += mg[s][v]; }
        for (int v = 0; v < 8; v++) mg[s][v] /= sum;
    }
    for (int v = 0; v < 8; v++) {
        float mx = -INFINITY;
        for (int s = 0; s < 8; s++) mx = fmaxf(mx, g_Sg[s*8+v]);
        float sum = 0.f;
        for (int s = 0; s < 8; s++) { mgT[v][s] = expf(g_Sg[s*8+v]-mx); sum += mgT[v][s]; }
        for (int s = 0; s < 8; s++) mgT[v][s] /= sum;
    }
    for (int s = 0; s < 8; s++) {
        float mx = -INFINITY;
        for (int v = 0; v < 8; v++) mx = fmaxf(mx, g_Sc[s*8+v]);
        float sum = 0.f;
        for (int v = 0; v < 8; v++) { mc[s][v] = expf(g_Sc[s*8+v]-mx); sum += mc[s][v]; }
        for (int v = 0; v < 8; v++) mc[s][v] /= sum;
    }
    float loss = 0.f;
    for (int s = 0; s < 8; s++) {
        float t = 0.f;
        for (int v = 0; v < 8; v++) t += mg[s][v]*mc[s][v];
        loss += logf(t);
    }
    for (int v = 0; v < 8; v++) {
        float t = 0.f;
        for (int s = 0; s < 8; s++) t += mgT[v][s]*mc[v][s];
        loss += logf(t);
    }
    out[0] = -loss/(float)ND;
}

// ---------------- host ----------------
extern "C" void kernel_launch(void* const* d_in, const int* in_sizes, int n_in,
                              void* d_out, int out_size)
{
    const float* doc  = (const float*)d_in[0];
    const float* img  = (const float*)d_in[1];
    const float* tm   = (const float*)d_in[2];
    const float* im   = (const float*)d_in[3];
    const float* se   = (const float*)d_in[4];
    const float* cont = (const float*)d_in[5];
    const int*   width= (const int*)  d_in[6];
    const float* m1   = (const float*)d_in[7];
    const float* aw1  = (const float*)d_in[8];
    const float* ab1  = (const float*)d_in[9];
    const float* aw2  = (const float*)d_in[10];
    const float* ab2  = (const float*)d_in[11];
    const float* wemb = (const float*)d_in[12];
    const float* pw1  = (const float*)d_in[13];
    const float* pb1  = (const float*)d_in[14];
    const float* pw2  = (const float*)d_in[15];
    const float* pb2  = (const float*)d_in[16];
    const float* pw3  = (const float*)d_in[17];
    const float* pb3  = (const float*)d_in[18];

    // grounding path (independent; run first)
    att_kernel<<<64, 256>>>(doc, img);
    ground_reduce<<<64, 64>>>(tm, im);

    // span attention: h = relu(cont @ aw1 + ab1); scores = h @ aw2 + ab2
    gemm_kernel<1,0,0><<<dim3(HH/BN, 1280/BM), 256>>>(cont, aw1, ab1, 1280, HH, BH);
    zero_ab_kernel<<<128, 256>>>();
    matvec1024<0><<<(1280*32+255)/256, 256>>>(aw2, ab2, 1280);
    assemble_kernel<<<NSPAN, 256>>>(se, cont, width, wemb);

    // a,b = spans @ w1 halves (fused, split-K)
    gemm_ab_kernel<<<dim3(2048/BN, KS), 256>>>(pw1);
    // h1 = relu(prod @ w1[2SD:] + a + b + b1)
    gemm_kernel<2,1,3><<<dim3(HH/BN, NPAIR/BM), 256>>>(nullptr, pw1 + (long)2*SD*HH, pb1, NPAIR, HH, SD);
    // h2 = relu(h1 @ w2 + b2)
    gemm_kernel<1,2,4><<<dim3(HH/BN, NPAIR/BM), 256>>>(nullptr, pw2, pb2, NPAIR, HH, HH);
    // ts = h2 @ w3 + b3
    matvec1024<1><<<(NPAIR*32+255)/256, 256>>>(pw3, pb3, NPAIR);

    // adaptive S_c + final loss
    sc_kernel<<<64, 32>>>(m1);
    loss_kernel<<<1, 32>>>((float*)d_out);
}